// round 4
// baseline (speedup 1.0000x reference)
#include <cuda_runtime.h>
#include <math.h>
#include <stdint.h>

// Shapes (fixed): B=2, S=2048, E=1024, H=16, D=64
static __device__ float g_K[2 * 16 * 2048 * 64];
static __device__ float g_V[2 * 16 * 2048 * 64];
// tf32 hi/lo fragment-image planes:
//   A-images: [mb(32)][kt(32)] blocks of 32KB (hi 16KB | lo 16KB)
//   B-images: [nb(8)][kt(32)] blocks of 32KB
static __device__ float g_xA[8 * 1024 * 1024];   // x as A operand (32MB)
static __device__ float g_OA[8 * 1024 * 1024];   // attention out as A operand (32MB)
static __device__ float g_WkB[2 * 1024 * 1024];  // 8MB
static __device__ float g_WvB[2 * 1024 * 1024];
static __device__ float g_WoB[2 * 1024 * 1024];

__device__ __forceinline__ float fast_exp2(float x) {
    float y;
    asm("ex2.approx.ftz.f32 %0, %1;" : "=f"(y) : "f"(x));
    return y;
}
__device__ __forceinline__ uint32_t tf32_of(float x) {
    uint32_t r;
    asm("cvt.rna.tf32.f32 %0, %1;" : "=r"(r) : "f"(x));
    return r;
}
__device__ __forceinline__ void mma16n8k8(float c[4], const uint32_t a[4],
                                          const uint32_t b[2]) {
    asm volatile(
        "mma.sync.aligned.m16n8k8.row.col.f32.tf32.tf32.f32 "
        "{%0,%1,%2,%3}, {%4,%5,%6,%7}, {%8,%9}, {%0,%1,%2,%3};"
        : "+f"(c[0]), "+f"(c[1]), "+f"(c[2]), "+f"(c[3])
        : "r"(a[0]), "r"(a[1]), "r"(a[2]), "r"(a[3]), "r"(b[0]), "r"(b[1]));
}
__device__ __forceinline__ uint32_t smem_u32(const void* p) {
    uint32_t a;
    asm("{ .reg .u64 t; cvta.to.shared.u64 t, %1; cvt.u32.u64 %0, t; }"
        : "=r"(a) : "l"(p));
    return a;
}

#define SW128(o) ((o) ^ (((o) >> 3) & 0x70))
#define CP16(d, s) \
    asm volatile("cp.async.cg.shared.global [%0], [%1], 16;" ::"r"(d), "l"(s) : "memory")
#define CP_COMMIT() asm volatile("cp.async.commit_group;" ::: "memory")
#define CP_WAIT1() asm volatile("cp.async.wait_group 1;" ::: "memory")
#define CP_WAIT0() asm volatile("cp.async.wait_group 0;" ::: "memory")

// Byte offsets inside a 16KB plane for a 128x32 tile (SW128 pre-applied).
__device__ __forceinline__ uint32_t A_off(int row, int k) {
    uint32_t tile = (uint32_t)(row >> 4);
    uint32_t k8 = (uint32_t)(k >> 3);
    uint32_t lane = (uint32_t)(((row & 7) << 2) | (k & 3));
    uint32_t slot = (uint32_t)((((k >> 2) & 1) << 1) | ((row >> 3) & 1));
    uint32_t off = ((k8 * 8 + tile) << 9) + (lane << 4) + (slot << 2);
    return SW128(off);
}
__device__ __forceinline__ uint32_t B_off(int n, int k) {
    uint32_t tile = (uint32_t)(n >> 3);
    uint32_t k8 = (uint32_t)(k >> 3);
    uint32_t lane = (uint32_t)(((n & 7) << 2) | (k & 3));
    uint32_t cc = (uint32_t)((k >> 2) & 1);
    uint32_t off = ((k8 * 16 + tile) << 8) + (lane << 3) + (cc << 2);
    return SW128(off);
}

// ---------------------------------------------------------------------------
// Split kernel: fp32 -> tf32 hi/lo fragment-image planes.
// grid (kt=32, mb=32, z=4): z=0 x->A-images, z=1..3 Wk/Wv/Wo -> B-images.
// ---------------------------------------------------------------------------
__global__ __launch_bounds__(128) void split_kernel(const float* __restrict__ x,
                                                    const float* __restrict__ Wk,
                                                    const float* __restrict__ Wv,
                                                    const float* __restrict__ Wo) {
    const int z = blockIdx.z;
    const int mb = blockIdx.y;
    const int kt = blockIdx.x;
    const float* src;
    float* dst;
    int isA;
    if (z == 0) {
        src = x; dst = g_xA; isA = 1;
    } else {
        if (mb >= 8) return;
        src = (z == 1) ? Wk : (z == 2) ? Wv : Wo;
        dst = (z == 1) ? g_WkB : (z == 2) ? g_WvB : g_WoB;
        isA = 0;
    }
    char* blk = (char*)(dst + ((size_t)(mb * 32 + kt)) * 8192);
    const int tid = threadIdx.x;
#pragma unroll
    for (int e = 0; e < 32; e++) {
        int idx = e * 128 + tid;
        int row = idx >> 5;
        int k = idx & 31;
        float v = src[(size_t)(mb * 128 + row) * 1024 + kt * 32 + k];
        uint32_t hi = tf32_of(v);
        uint32_t lo = tf32_of(v - __uint_as_float(hi));
        uint32_t off = isA ? A_off(row, k) : B_off(row, k);
        *reinterpret_cast<uint32_t*>(blk + off) = hi;
        *reinterpret_cast<uint32_t*>(blk + 16384 + off) = lo;
    }
}

// ---------------------------------------------------------------------------
// Image GEMM: C[m,n] = sum_k A[m,k]*W[n,k] in 3xTF32, inputs pre-split images.
// CTA tile 128x128, K=1024 in 32 tiles; 2-stage cp.async pipeline.
// SMEM stage (64KB): Ahi 16K | Alo 16K | Bhi 16K | Blo 16K; 2 stages = 128KB.
// Warp layout 4(M)x2(N), warp tile 32x64.
// ---------------------------------------------------------------------------
#define AHI 0
#define ALO 16384
#define BHI 32768
#define BLO 49152
#define GM_SMEM_BYTES 131072

__device__ void gemm_img_body(const float* __restrict__ Aimg,
                              const float* __restrict__ Bimg,
                              float* __restrict__ Cout, int remap) {
    extern __shared__ __align__(1024) char smc[];
    const uint32_t sbase = smem_u32(smc);
    const int tid = threadIdx.x;
    const int lane = tid & 31;
    const int wid = tid >> 5;
    const int warpM = wid & 3;
    const int warpN = wid >> 2;
    const int mb = blockIdx.y;
    const int nb = blockIdx.x;

    float c[2][8][4];
#pragma unroll
    for (int i = 0; i < 2; i++)
#pragma unroll
        for (int j = 0; j < 8; j++)
#pragma unroll
            for (int q = 0; q < 4; q++) c[i][j][q] = 0.0f;

    const char* Abase = (const char*)(Aimg) + (size_t)mb * 32 * 32768;
    const char* Bbase = (const char*)(Bimg) + (size_t)nb * 32 * 32768;

    // issue loads for K-tile kt into buffer kt&1
    auto issue = [&](int kt) {
        uint32_t dA = sbase + (uint32_t)((kt & 1) * 65536) + (uint32_t)tid * 128;
        const char* sA = Abase + (size_t)kt * 32768 + tid * 128;
        uint32_t dB = dA + 32768;
        const char* sB = Bbase + (size_t)kt * 32768 + tid * 128;
#pragma unroll
        for (int j = 0; j < 8; j++) CP16(dA + j * 16, sA + j * 16);
#pragma unroll
        for (int j = 0; j < 8; j++) CP16(dB + j * 16, sB + j * 16);
        CP_COMMIT();
    };

    issue(0);
    for (int kt = 0; kt < 32; kt++) {
        if (kt < 31) {
            issue(kt + 1);
            CP_WAIT1();
        } else {
            CP_WAIT0();
        }
        __syncthreads();
        char* smb = smc + (kt & 1) * 65536;

#pragma unroll
        for (int k8 = 0; k8 < 4; k8++) {
            uint32_t ah[2][4], al[2][4], bh[8][2], bl[8][2];
#pragma unroll
            for (int tm = 0; tm < 2; tm++) {
                uint32_t tile = warpM * 2 + tm;
                uint32_t off = SW128((uint32_t)(k8 * 8 + tile) * 512 + lane * 16);
                uint4 h = *reinterpret_cast<const uint4*>(smb + AHI + off);
                ah[tm][0] = h.x; ah[tm][1] = h.y; ah[tm][2] = h.z; ah[tm][3] = h.w;
                uint4 l = *reinterpret_cast<const uint4*>(smb + ALO + off);
                al[tm][0] = l.x; al[tm][1] = l.y; al[tm][2] = l.z; al[tm][3] = l.w;
            }
#pragma unroll
            for (int tn = 0; tn < 8; tn++) {
                uint32_t tile = warpN * 8 + tn;
                uint32_t off = SW128((uint32_t)(k8 * 16 + tile) * 256 + lane * 8);
                uint2 h = *reinterpret_cast<const uint2*>(smb + BHI + off);
                bh[tn][0] = h.x; bh[tn][1] = h.y;
                uint2 l = *reinterpret_cast<const uint2*>(smb + BLO + off);
                bl[tn][0] = l.x; bl[tn][1] = l.y;
            }
#pragma unroll
            for (int tm = 0; tm < 2; tm++)
#pragma unroll
                for (int tn = 0; tn < 8; tn++) {
                    mma16n8k8(c[tm][tn], ah[tm], bh[tn]);
                    mma16n8k8(c[tm][tn], ah[tm], bl[tn]);
                    mma16n8k8(c[tm][tn], al[tm], bh[tn]);
                }
        }
        __syncthreads();
    }

    // Epilogue: rows = mb*128+warpM*32+tm*16+{g,g+8}, cols = nb*128+warpN*64+tn*8+t4*2+{0,1}
    const int g = lane >> 2;
    const int t4 = lane & 3;
    const int bm = mb * 128;
    const int bn = nb * 128;
#pragma unroll
    for (int tm = 0; tm < 2; tm++) {
#pragma unroll
        for (int tn = 0; tn < 8; tn++) {
            int row0 = bm + warpM * 32 + tm * 16 + g;
            int col = bn + warpN * 64 + tn * 8 + t4 * 2;
#pragma unroll
            for (int hrow = 0; hrow < 2; hrow++) {
                int m = row0 + hrow * 8;
                float2 v = make_float2(c[tm][tn][2 * hrow], c[tm][tn][2 * hrow + 1]);
                if (remap) {
                    int bb = m >> 11;
                    int s = m & 2047;
                    int h = col >> 6;
                    int d = col & 63;
                    *reinterpret_cast<float2*>(
                        Cout + ((size_t)((bb << 4) + h) * 2048 + s) * 64 + d) = v;
                } else {
                    *reinterpret_cast<float2*>(Cout + (size_t)m * 1024 + col) = v;
                }
            }
        }
    }
}

__global__ __launch_bounds__(256, 1) void proj_img_kernel() {
    const float* Bimg = (blockIdx.z == 0) ? g_WkB : g_WvB;
    float* C = (blockIdx.z == 0) ? g_K : g_V;
    gemm_img_body(g_xA, Bimg, C, 1);
}
__global__ __launch_bounds__(256, 1) void oproj_img_kernel(float* __restrict__ out) {
    gemm_img_body(g_OA, g_WoB, out, 0);
}

// ---------------------------------------------------------------------------
// Attention (fp32 flash-style): logits = K V^T * (-32), softmax, P V.
// Epilogue writes tf32 hi/lo A-images into g_OA for the output projection.
// ---------------------------------------------------------------------------
#define SKT_OFF 0
#define SVD_OFF 8448
#define SVK_OFF 16896
#define SP_OFF 25600
#define ATTN_SMEM_BYTES (42496 * 4)

__global__ __launch_bounds__(256, 1) void attn_kernel() {
    extern __shared__ float sm[];
    float* sKt = sm + SKT_OFF;
    float* sVd = sm + SVD_OFF;
    float* sVk = sm + SVK_OFF;
    float* sP = sm + SP_OFF;

    const int tid = threadIdx.x;
    const int tx = tid & 15;
    const int ty = tid >> 4;
    const int hb = blockIdx.y;
    const int r0 = blockIdx.x * 128;
    const float* Kh = g_K + (size_t)hb * 2048 * 64;
    const float* Vh = g_V + (size_t)hb * 2048 * 64;
    const float SC = -32.0f * 1.4426950408889634f;

#pragma unroll
    for (int it = 0; it < 8; it++) {
        int f = tid + it * 256;
        int row = f >> 4;
        int d4 = (f & 15) << 2;
        float4 v = *reinterpret_cast<const float4*>(Kh + (size_t)(r0 + row) * 64 + d4);
        sKt[(d4 + 0) * 132 + row] = v.x;
        sKt[(d4 + 1) * 132 + row] = v.y;
        sKt[(d4 + 2) * 132 + row] = v.z;
        sKt[(d4 + 3) * 132 + row] = v.w;
    }

    float m_i[8], l_i[8], o[8][4];
#pragma unroll
    for (int i = 0; i < 8; i++) {
        m_i[i] = -INFINITY;
        l_i[i] = 0.0f;
#pragma unroll
        for (int j = 0; j < 4; j++) o[i][j] = 0.0f;
    }

    for (int c0 = 0; c0 < 2048; c0 += 128) {
        __syncthreads();
#pragma unroll
        for (int it = 0; it < 8; it++) {
            int f = tid + it * 256;
            int key = f >> 4;
            int d4 = (f & 15) << 2;
            float4 v = *reinterpret_cast<const float4*>(Vh + (size_t)(c0 + key) * 64 + d4);
            *reinterpret_cast<float4*>(&sVk[key * 68 + d4]) = v;
            sVd[(d4 + 0) * 132 + key] = v.x;
            sVd[(d4 + 1) * 132 + key] = v.y;
            sVd[(d4 + 2) * 132 + key] = v.z;
            sVd[(d4 + 3) * 132 + key] = v.w;
        }
        __syncthreads();

        float s[8][8];
#pragma unroll
        for (int i = 0; i < 8; i++)
#pragma unroll
            for (int j = 0; j < 8; j++) s[i][j] = 0.0f;
#pragma unroll
        for (int k = 0; k < 64; k++) {
            float4 a0 = *reinterpret_cast<const float4*>(&sKt[k * 132 + ty * 8]);
            float4 a1 = *reinterpret_cast<const float4*>(&sKt[k * 132 + ty * 8 + 4]);
            float4 b0 = *reinterpret_cast<const float4*>(&sVd[k * 132 + tx * 8]);
            float4 b1 = *reinterpret_cast<const float4*>(&sVd[k * 132 + tx * 8 + 4]);
            float a[8] = {a0.x, a0.y, a0.z, a0.w, a1.x, a1.y, a1.z, a1.w};
            float b[8] = {b0.x, b0.y, b0.z, b0.w, b1.x, b1.y, b1.z, b1.w};
#pragma unroll
            for (int i = 0; i < 8; i++)
#pragma unroll
                for (int j = 0; j < 8; j++)
                    s[i][j] = fmaf(a[i], b[j], s[i][j]);
        }

#pragma unroll
        for (int i = 0; i < 8; i++)
#pragma unroll
            for (int j = 0; j < 8; j++) s[i][j] *= SC;

#pragma unroll
        for (int i = 0; i < 8; i++) {
            float mx = s[i][0];
#pragma unroll
            for (int j = 1; j < 8; j++) mx = fmaxf(mx, s[i][j]);
#pragma unroll
            for (int off = 1; off < 16; off <<= 1)
                mx = fmaxf(mx, __shfl_xor_sync(0xffffffffu, mx, off));
            float mn = fmaxf(m_i[i], mx);
            float al = fast_exp2(m_i[i] - mn);
            m_i[i] = mn;
            float rs = 0.0f;
#pragma unroll
            for (int j = 0; j < 8; j++) {
                float pp = fast_exp2(s[i][j] - mn);
                s[i][j] = pp;
                rs += pp;
            }
#pragma unroll
            for (int off = 1; off < 16; off <<= 1)
                rs += __shfl_xor_sync(0xffffffffu, rs, off);
            l_i[i] = l_i[i] * al + rs;
#pragma unroll
            for (int j = 0; j < 4; j++) o[i][j] *= al;
        }

#pragma unroll
        for (int i = 0; i < 8; i++) {
            *reinterpret_cast<float4*>(&sP[(ty * 8 + i) * 132 + tx * 8]) =
                make_float4(s[i][0], s[i][1], s[i][2], s[i][3]);
            *reinterpret_cast<float4*>(&sP[(ty * 8 + i) * 132 + tx * 8 + 4]) =
                make_float4(s[i][4], s[i][5], s[i][6], s[i][7]);
        }
        __syncthreads();

#pragma unroll 8
        for (int k2 = 0; k2 < 128; k2 += 4) {
            float areg[8][4];
#pragma unroll
            for (int i = 0; i < 8; i++) {
                float4 t = *reinterpret_cast<const float4*>(&sP[(ty * 8 + i) * 132 + k2]);
                areg[i][0] = t.x; areg[i][1] = t.y; areg[i][2] = t.z; areg[i][3] = t.w;
            }
#pragma unroll
            for (int kk = 0; kk < 4; kk++) {
                float4 bv = *reinterpret_cast<const float4*>(&sVk[(k2 + kk) * 68 + tx * 4]);
#pragma unroll
                for (int i = 0; i < 8; i++) {
                    o[i][0] = fmaf(areg[i][kk], bv.x, o[i][0]);
                    o[i][1] = fmaf(areg[i][kk], bv.y, o[i][1]);
                    o[i][2] = fmaf(areg[i][kk], bv.z, o[i][2]);
                    o[i][3] = fmaf(areg[i][kk], bv.w, o[i][3]);
                }
            }
        }
    }

    // Epilogue: write tf32 hi/lo A-images into g_OA (rows m=b*2048+s, k=h*64+d)
    const int b = hb >> 4;
    const int h = hb & 15;
#pragma unroll
    for (int i = 0; i < 8; i++) {
        float inv = 1.0f / l_i[i];
        int m = b * 2048 + r0 + ty * 8 + i;
        int mbb = m >> 7;
        int mr = m & 127;
#pragma unroll
        for (int j = 0; j < 4; j++) {
            int k = h * 64 + tx * 4 + j;
            int kt = k >> 5;
            int kk = k & 31;
            float v = o[i][j] * inv;
            uint32_t hi = tf32_of(v);
            uint32_t lo = tf32_of(v - __uint_as_float(hi));
            char* blk = (char*)(g_OA + ((size_t)(mbb * 32 + kt)) * 8192);
            uint32_t off = A_off(mr, kk);
            *reinterpret_cast<uint32_t*>(blk + off) = hi;
            *reinterpret_cast<uint32_t*>(blk + 16384 + off) = lo;
        }
    }
}

extern "C" void kernel_launch(void* const* d_in, const int* in_sizes, int n_in,
                              void* d_out, int out_size) {
    const float* x = (const float*)d_in[0];
    // d_in[1] = Wq (dead code in the reference dataflow)
    const float* Wk = (const float*)d_in[2];
    const float* Wv = (const float*)d_in[3];
    const float* Wo = (const float*)d_in[4];
    float* out = (float*)d_out;

    cudaFuncSetAttribute(proj_img_kernel, cudaFuncAttributeMaxDynamicSharedMemorySize,
                         GM_SMEM_BYTES);
    cudaFuncSetAttribute(oproj_img_kernel, cudaFuncAttributeMaxDynamicSharedMemorySize,
                         GM_SMEM_BYTES);
    cudaFuncSetAttribute(attn_kernel, cudaFuncAttributeMaxDynamicSharedMemorySize,
                         ATTN_SMEM_BYTES);

    // 1) Pre-split inputs into tf32 hi/lo fragment images
    split_kernel<<<dim3(32, 32, 4), 128>>>(x, Wk, Wv, Wo);

    // 2) K/V projections (image GEMM, 3xTF32 mma)
    proj_img_kernel<<<dim3(8, 32, 2), 256, GM_SMEM_BYTES>>>();

    // 3) Attention (fp32), writes g_OA images
    attn_kernel<<<dim3(16, 32), 256, ATTN_SMEM_BYTES>>>();

    // 4) Output projection (image GEMM)
    oproj_img_kernel<<<dim3(8, 32), 256, GM_SMEM_BYTES>>>(out);
}

// round 7
// speedup vs baseline: 1.0761x; 1.0761x over previous
#include <cuda_runtime.h>
#include <math.h>
#include <stdint.h>

// Shapes (fixed): B=2, S=2048, E=1024, H=16, D=64
// tf32 hi/lo fragment-image planes (all sizes in floats):
//  g_xA : x as A operand    [mb(32)][kt(32)] blocks of 32KB (hi16K|lo16K)
//  g_OA : attn out as A op  same layout
//  g_W*B: weights as B op   [nb(8)][kt(32)] blocks of 32KB
//  g_KA : K as A operand    [hb(32)][mb(16)][kt(2)] blocks of 32KB
//  g_VSB: V as S-GEMM B op  [hb(32)][kb(32)][kt(2)] blocks of 16KB (hi8K|lo8K), n=key64,k=d32
//  g_VPB: V as PV-GEMM B op [hb(32)][kkt(64)] blocks of 16KB (hi8K|lo8K), n=d64,k=key32
static __device__ float g_xA[8 * 1024 * 1024];
static __device__ float g_OA[8 * 1024 * 1024];
static __device__ float g_WkB[2 * 1024 * 1024];
static __device__ float g_WvB[2 * 1024 * 1024];
static __device__ float g_WoB[2 * 1024 * 1024];
static __device__ float g_KA[8 * 1024 * 1024];
static __device__ float g_VSB[8 * 1024 * 1024];
static __device__ float g_VPB[8 * 1024 * 1024];

__device__ __forceinline__ float fast_exp2(float x) {
    float y;
    asm("ex2.approx.ftz.f32 %0, %1;" : "=f"(y) : "f"(x));
    return y;
}
__device__ __forceinline__ uint32_t tf32_of(float x) {
    uint32_t r;
    asm("cvt.rna.tf32.f32 %0, %1;" : "=r"(r) : "f"(x));
    return r;
}
__device__ __forceinline__ void mma16n8k8(float c[4], const uint32_t a[4],
                                          const uint32_t b[2]) {
    asm volatile(
        "mma.sync.aligned.m16n8k8.row.col.f32.tf32.tf32.f32 "
        "{%0,%1,%2,%3}, {%4,%5,%6,%7}, {%8,%9}, {%0,%1,%2,%3};"
        : "+f"(c[0]), "+f"(c[1]), "+f"(c[2]), "+f"(c[3])
        : "r"(a[0]), "r"(a[1]), "r"(a[2]), "r"(a[3]), "r"(b[0]), "r"(b[1]));
}
__device__ __forceinline__ uint32_t smem_u32(const void* p) {
    uint32_t a;
    asm("{ .reg .u64 t; cvta.to.shared.u64 t, %1; cvt.u32.u64 %0, t; }"
        : "=r"(a) : "l"(p));
    return a;
}

#define SW128(o) ((o) ^ (((o) >> 3) & 0x70))
#define CP16(d, s) \
    asm volatile("cp.async.cg.shared.global [%0], [%1], 16;" ::"r"(d), "l"(s) : "memory")
#define CP_COMMIT() asm volatile("cp.async.commit_group;" ::: "memory")
#define CP_WAIT(n) asm volatile("cp.async.wait_group %0;" ::"n"(n) : "memory")

// A-image byte offset inside a 16KB plane (128 rows x 32 k)
__device__ __forceinline__ uint32_t A_off(int row, int k) {
    uint32_t tile = (uint32_t)(row >> 4);
    uint32_t k8 = (uint32_t)(k >> 3);
    uint32_t lane = (uint32_t)(((row & 7) << 2) | (k & 3));
    uint32_t slot = (uint32_t)((((k >> 2) & 1) << 1) | ((row >> 3) & 1));
    return SW128(((k8 * 8 + tile) << 9) + (lane << 4) + (slot << 2));
}
// B-image byte offset inside a 16KB plane (128 n x 32 k)
__device__ __forceinline__ uint32_t B_off(int n, int k) {
    uint32_t tile = (uint32_t)(n >> 3);
    uint32_t k8 = (uint32_t)(k >> 3);
    uint32_t lane = (uint32_t)(((n & 7) << 2) | (k & 3));
    uint32_t cc = (uint32_t)((k >> 2) & 1);
    return SW128(((k8 * 16 + tile) << 8) + (lane << 3) + (cc << 2));
}
// B-image byte offset inside an 8KB plane (64 n x 32 k)
__device__ __forceinline__ uint32_t B_off64(int n, int k) {
    uint32_t tile = (uint32_t)(n >> 3);
    uint32_t k8 = (uint32_t)(k >> 3);
    uint32_t lane = (uint32_t)(((n & 7) << 2) | (k & 3));
    uint32_t cc = (uint32_t)((k >> 2) & 1);
    return SW128(((k8 * 8 + tile) << 8) + (lane << 3) + (cc << 2));
}

// ---------------------------------------------------------------------------
// Split kernel: fp32 -> tf32 hi/lo fragment images (x -> A, Wk/Wv/Wo -> B).
// ---------------------------------------------------------------------------
__global__ __launch_bounds__(128) void split_kernel(const float* __restrict__ x,
                                                    const float* __restrict__ Wk,
                                                    const float* __restrict__ Wv,
                                                    const float* __restrict__ Wo) {
    const int z = blockIdx.z;
    const int mb = blockIdx.y;
    const int kt = blockIdx.x;
    const float* src;
    float* dst;
    int isA;
    if (z == 0) {
        src = x; dst = g_xA; isA = 1;
    } else {
        if (mb >= 8) return;
        src = (z == 1) ? Wk : (z == 2) ? Wv : Wo;
        dst = (z == 1) ? g_WkB : (z == 2) ? g_WvB : g_WoB;
        isA = 0;
    }
    char* blk = (char*)(dst + ((size_t)(mb * 32 + kt)) * 8192);
    const int tid = threadIdx.x;
#pragma unroll
    for (int e = 0; e < 32; e++) {
        int idx = e * 128 + tid;
        int row = idx >> 5;
        int k = idx & 31;
        float v = src[(size_t)(mb * 128 + row) * 1024 + kt * 32 + k];
        uint32_t hi = tf32_of(v);
        uint32_t lo = tf32_of(v - __uint_as_float(hi));
        uint32_t off = isA ? A_off(row, k) : B_off(row, k);
        *reinterpret_cast<uint32_t*>(blk + off) = hi;
        *reinterpret_cast<uint32_t*>(blk + 16384 + off) = lo;
    }
}

// ---------------------------------------------------------------------------
// Image GEMM: C[m,n] = sum_k A[m,k]*W[n,k] (3xTF32). CTA tile 128x128, K=1024.
// 512 threads, 16 warps = 4(M) x 4(N), warp tile 32x32. 3-stage cp.async.
// Stage (64KB): Ahi 16K | Alo 16K | Bhi 16K | Blo 16K.
// wmode: 0 = plain row-major, 1 = K images, 2 = V images.
// ---------------------------------------------------------------------------
#define GM_SMEM_BYTES (3 * 65536)

__device__ __forceinline__ void wr_K_img(int m, int col, float v) {
    int s = m & 2047;
    int hb = ((m >> 11) << 4) + (col >> 6);
    int d = col & 63;
    char* blk = (char*)g_KA + ((size_t)((hb * 16 + (s >> 7)) * 2 + (d >> 5))) * 32768;
    uint32_t off = A_off(s & 127, d & 31);
    uint32_t hi = tf32_of(v);
    uint32_t lo = tf32_of(v - __uint_as_float(hi));
    *reinterpret_cast<uint32_t*>(blk + off) = hi;
    *reinterpret_cast<uint32_t*>(blk + 16384 + off) = lo;
}
__device__ __forceinline__ void wr_V_img(int m, int col, float v) {
    int s = m & 2047;
    int hb = ((m >> 11) << 4) + (col >> 6);
    int d = col & 63;
    uint32_t hi = tf32_of(v);
    uint32_t lo = tf32_of(v - __uint_as_float(hi));
    {
        char* blk = (char*)g_VSB +
                    ((size_t)((hb * 32 + (s >> 6)) * 2 + (d >> 5))) * 16384;
        uint32_t off = B_off64(s & 63, d & 31);
        *reinterpret_cast<uint32_t*>(blk + off) = hi;
        *reinterpret_cast<uint32_t*>(blk + 8192 + off) = lo;
    }
    {
        char* blk = (char*)g_VPB + ((size_t)(hb * 64 + (s >> 5))) * 16384;
        uint32_t off = B_off64(d, s & 31);
        *reinterpret_cast<uint32_t*>(blk + off) = hi;
        *reinterpret_cast<uint32_t*>(blk + 8192 + off) = lo;
    }
}

__device__ void gemm_img_body(const float* __restrict__ Aimg,
                              const float* __restrict__ Bimg,
                              float* __restrict__ Cout, int wmode) {
    extern __shared__ __align__(1024) char smc[];
    const uint32_t sbase = smem_u32(smc);
    const int tid = threadIdx.x;
    const int lane = tid & 31;
    const int wid = tid >> 5;
    const int warpM = wid & 3;
    const int warpN = wid >> 2;
    const int mb = blockIdx.y;
    const int nb = blockIdx.x;

    float c[2][4][4];
#pragma unroll
    for (int i = 0; i < 2; i++)
#pragma unroll
        for (int j = 0; j < 4; j++)
#pragma unroll
            for (int q = 0; q < 4; q++) c[i][j][q] = 0.0f;

    const char* Abase = (const char*)(Aimg) + (size_t)mb * 32 * 32768;
    const char* Bbase = (const char*)(Bimg) + (size_t)nb * 32 * 32768;

    auto issue = [&](int kt) {
        int st = kt % 3;
        if (tid < 256) {
            uint32_t d = sbase + (uint32_t)(st * 65536) + (uint32_t)tid * 128;
            const char* s = Abase + (size_t)kt * 32768 + tid * 128;
#pragma unroll
            for (int j = 0; j < 8; j++) CP16(d + j * 16, s + j * 16);
        } else {
            uint32_t d = sbase + (uint32_t)(st * 65536 + 32768) +
                         (uint32_t)(tid - 256) * 128;
            const char* s = Bbase + (size_t)kt * 32768 + (tid - 256) * 128;
#pragma unroll
            for (int j = 0; j < 8; j++) CP16(d + j * 16, s + j * 16);
        }
        CP_COMMIT();
    };

    issue(0);
    issue(1);
    for (int kt = 0; kt < 32; kt++) {
        if (kt < 31) CP_WAIT(1); else CP_WAIT(0);
        __syncthreads();
        char* smb = smc + (kt % 3) * 65536;

#pragma unroll
        for (int k8 = 0; k8 < 4; k8++) {
            uint32_t ah[2][4], al[2][4], bh[4][2], bl[4][2];
#pragma unroll
            for (int tm = 0; tm < 2; tm++) {
                uint32_t tile = warpM * 2 + tm;
                uint32_t off = SW128((uint32_t)(k8 * 8 + tile) * 512 + lane * 16);
                uint4 h = *reinterpret_cast<const uint4*>(smb + off);
                ah[tm][0] = h.x; ah[tm][1] = h.y; ah[tm][2] = h.z; ah[tm][3] = h.w;
                uint4 l = *reinterpret_cast<const uint4*>(smb + 16384 + off);
                al[tm][0] = l.x; al[tm][1] = l.y; al[tm][2] = l.z; al[tm][3] = l.w;
            }
#pragma unroll
            for (int tn = 0; tn < 4; tn++) {
                uint32_t tile = warpN * 4 + tn;
                uint32_t off = SW128((uint32_t)(k8 * 16 + tile) * 256 + lane * 8);
                uint2 h = *reinterpret_cast<const uint2*>(smb + 32768 + off);
                bh[tn][0] = h.x; bh[tn][1] = h.y;
                uint2 l = *reinterpret_cast<const uint2*>(smb + 49152 + off);
                bl[tn][0] = l.x; bl[tn][1] = l.y;
            }
#pragma unroll
            for (int tm = 0; tm < 2; tm++)
#pragma unroll
                for (int tn = 0; tn < 4; tn++) {
                    mma16n8k8(c[tm][tn], ah[tm], bh[tn]);
                    mma16n8k8(c[tm][tn], ah[tm], bl[tn]);
                    mma16n8k8(c[tm][tn], al[tm], bh[tn]);
                }
        }
        __syncthreads();
        if (kt < 30) issue(kt + 2);
    }

    const int g = lane >> 2;
    const int t4 = lane & 3;
    const int bm = mb * 128;
    const int bn = nb * 128;
#pragma unroll
    for (int tm = 0; tm < 2; tm++) {
#pragma unroll
        for (int tn = 0; tn < 4; tn++) {
            int row0 = bm + warpM * 32 + tm * 16 + g;
            int col = bn + warpN * 32 + tn * 8 + t4 * 2;
#pragma unroll
            for (int hrow = 0; hrow < 2; hrow++) {
                int m = row0 + hrow * 8;
                float v0 = c[tm][tn][2 * hrow];
                float v1 = c[tm][tn][2 * hrow + 1];
                if (wmode == 1) {
                    wr_K_img(m, col, v0);
                    wr_K_img(m, col + 1, v1);
                } else if (wmode == 2) {
                    wr_V_img(m, col, v0);
                    wr_V_img(m, col + 1, v1);
                } else {
                    *reinterpret_cast<float2*>(Cout + (size_t)m * 1024 + col) =
                        make_float2(v0, v1);
                }
            }
        }
    }
}

__global__ __launch_bounds__(512, 1) void proj_img_kernel() {
    if (blockIdx.z == 0)
        gemm_img_body(g_xA, g_WkB, nullptr, 1);
    else
        gemm_img_body(g_xA, g_WvB, nullptr, 2);
}
__global__ __launch_bounds__(512, 1) void oproj_img_kernel(float* __restrict__ out) {
    gemm_img_body(g_OA, g_WoB, out, 0);
}

// ---------------------------------------------------------------------------
// Tensor-core attention. Per (b,h), q-block of 128 rows (CTA), key-tiles of 64.
//   S = K·V^T (3xTF32), online softmax (base-2, scale folded), O += P_q·V.
// 256 threads = 8 warps; warp w owns rows w*16..w*16+15 (full softmax rows).
// SMEM: K images 64KB | P image 32KB (tf32 hi) | 2 stages x (VSB 32KB + VPB 32KB)
// All SMEM ld/st go through the generic pointer (smc); shared-space addresses
// (sbase+off) are used ONLY as cp.async destinations.
// ---------------------------------------------------------------------------
#define ATT_K 0
#define ATT_P 65536
#define ATT_STG 98304
#define ATT_SMEM_BYTES (98304 + 2 * 65536)

__global__ __launch_bounds__(256, 1) void attn_mma_kernel() {
    extern __shared__ __align__(1024) char smc[];
    const uint32_t sbase = smem_u32(smc);
    const int tid = threadIdx.x;
    const int lane = tid & 31;
    const int w = tid >> 5;
    const int g = lane >> 2;
    const int t4 = lane & 3;
    const int hb = blockIdx.y;
    const int mb = blockIdx.x;
    const float SC = -32.0f * 1.4426950408889634f;

    const char* KAg = (const char*)g_KA + (size_t)(hb * 16 + mb) * 65536;
    const char* VSBg = (const char*)g_VSB + (size_t)hb * 32 * 32768;
    const char* VPBg = (const char*)g_VPB + (size_t)hb * 64 * 16384;

    auto issue_stage = [&](int i) {
        int st = i & 1;
        if (tid < 128) {
            uint32_t d = sbase + (uint32_t)(ATT_STG + st * 65536) + (uint32_t)tid * 256;
            const char* s = VSBg + (size_t)i * 32768 + tid * 256;
#pragma unroll
            for (int j = 0; j < 16; j++) CP16(d + j * 16, s + j * 16);
        } else {
            uint32_t d = sbase + (uint32_t)(ATT_STG + st * 65536 + 32768) +
                         (uint32_t)(tid - 128) * 256;
            const char* s = VPBg + (size_t)(2 * i) * 16384 + (tid - 128) * 256;
#pragma unroll
            for (int j = 0; j < 16; j++) CP16(d + j * 16, s + j * 16);
        }
        CP_COMMIT();
    };

    // Prologue: K (64KB, joins group 0) + stage0, then stage1
    {
        uint32_t d = sbase + (uint32_t)tid * 256;
        const char* s = KAg + tid * 256;
#pragma unroll
        for (int j = 0; j < 16; j++) CP16(d + j * 16, s + j * 16);
    }
    issue_stage(0);
    issue_stage(1);

    float o[8][4];
#pragma unroll
    for (int tn = 0; tn < 8; tn++)
#pragma unroll
        for (int q = 0; q < 4; q++) o[tn][q] = 0.0f;
    float m0 = -INFINITY, m1 = -INFINITY, l0 = 0.0f, l1 = 0.0f;

    for (int i = 0; i < 32; i++) {
        if (i < 31) CP_WAIT(1); else CP_WAIT(0);
        __syncthreads();
        const uint32_t stg = (uint32_t)(ATT_STG + (i & 1) * 65536);

        // ---- S = K·V^T  (128 rows x 64 keys), 3xTF32 ----
        float s[8][4];
#pragma unroll
        for (int tn = 0; tn < 8; tn++)
#pragma unroll
            for (int q = 0; q < 4; q++) s[tn][q] = 0.0f;
#pragma unroll
        for (int k8 = 0; k8 < 8; k8++) {
            int kt = k8 >> 2;
            int k8i = k8 & 3;
            uint32_t aoff = (uint32_t)(ATT_K + kt * 32768) +
                            SW128((uint32_t)(k8i * 8 + w) * 512 + lane * 16);
            uint4 h4 = *reinterpret_cast<const uint4*>(smc + aoff);
            uint4 l4 = *reinterpret_cast<const uint4*>(smc + aoff + 16384);
            uint32_t ah[4] = {h4.x, h4.y, h4.z, h4.w};
            uint32_t al[4] = {l4.x, l4.y, l4.z, l4.w};
#pragma unroll
            for (int tn = 0; tn < 8; tn++) {
                uint32_t boff = stg + (uint32_t)(kt * 16384) +
                                SW128((uint32_t)(k8i * 8 + tn) * 256 + lane * 8);
                uint2 bh2 = *reinterpret_cast<const uint2*>(smc + boff);
                uint2 bl2 = *reinterpret_cast<const uint2*>(smc + boff + 8192);
                uint32_t bh[2] = {bh2.x, bh2.y};
                uint32_t bl[2] = {bl2.x, bl2.y};
                mma16n8k8(s[tn], ah, bh);
                mma16n8k8(s[tn], ah, bl);
                mma16n8k8(s[tn], al, bh);
            }
        }

        // ---- softmax over this 64-key tile (rows: w*16+g, w*16+g+8) ----
#pragma unroll
        for (int tn = 0; tn < 8; tn++)
#pragma unroll
            for (int q = 0; q < 4; q++) s[tn][q] *= SC;

        float mx0 = s[0][0], mx1 = s[0][2];
#pragma unroll
        for (int tn = 0; tn < 8; tn++) {
            mx0 = fmaxf(mx0, fmaxf(s[tn][0], s[tn][1]));
            mx1 = fmaxf(mx1, fmaxf(s[tn][2], s[tn][3]));
        }
        mx0 = fmaxf(mx0, __shfl_xor_sync(0xffffffffu, mx0, 1));
        mx0 = fmaxf(mx0, __shfl_xor_sync(0xffffffffu, mx0, 2));
        mx1 = fmaxf(mx1, __shfl_xor_sync(0xffffffffu, mx1, 1));
        mx1 = fmaxf(mx1, __shfl_xor_sync(0xffffffffu, mx1, 2));

        float mn0 = fmaxf(m0, mx0), mn1 = fmaxf(m1, mx1);
        float al0 = fast_exp2(m0 - mn0), al1 = fast_exp2(m1 - mn1);
        m0 = mn0; m1 = mn1;

        float rs0 = 0.0f, rs1 = 0.0f;
        const int r0 = w * 16 + g;
#pragma unroll
        for (int tn = 0; tn < 8; tn++) {
#pragma unroll
            for (int q = 0; q < 4; q++) {
                int key = tn * 8 + t4 * 2 + (q & 1);
                int row = r0 + ((q >> 1) << 3);
                float p = fast_exp2(s[tn][q] - ((q < 2) ? mn0 : mn1));
                uint32_t bits = tf32_of(p);
                float pq = __uint_as_float(bits);
                if (q < 2) rs0 += pq; else rs1 += pq;
                *reinterpret_cast<uint32_t*>(
                    smc + ATT_P + (key >> 5) * 16384 + A_off(row, key & 31)) = bits;
            }
        }
        rs0 += __shfl_xor_sync(0xffffffffu, rs0, 1);
        rs0 += __shfl_xor_sync(0xffffffffu, rs0, 2);
        rs1 += __shfl_xor_sync(0xffffffffu, rs1, 1);
        rs1 += __shfl_xor_sync(0xffffffffu, rs1, 2);
        l0 = l0 * al0 + rs0;
        l1 = l1 * al1 + rs1;
#pragma unroll
        for (int tn = 0; tn < 8; tn++) {
            o[tn][0] *= al0; o[tn][1] *= al0;
            o[tn][2] *= al1; o[tn][3] *= al1;
        }
        __syncwarp();

        // ---- O += P_q · V  (128 rows x 64 d, k = 64 keys) ----
#pragma unroll
        for (int k8 = 0; k8 < 8; k8++) {
            int kp = k8 >> 2;
            int k8i = k8 & 3;
            uint32_t poff = (uint32_t)(ATT_P + kp * 16384) +
                            SW128((uint32_t)(k8i * 8 + w) * 512 + lane * 16);
            uint4 p4 = *reinterpret_cast<const uint4*>(smc + poff);
            uint32_t pa[4] = {p4.x, p4.y, p4.z, p4.w};
#pragma unroll
            for (int tn = 0; tn < 8; tn++) {
                uint32_t voff = stg + (uint32_t)(32768 + kp * 16384) +
                                SW128((uint32_t)(k8i * 8 + tn) * 256 + lane * 8);
                uint2 vh2 = *reinterpret_cast<const uint2*>(smc + voff);
                uint2 vl2 = *reinterpret_cast<const uint2*>(smc + voff + 8192);
                uint32_t vh[2] = {vh2.x, vh2.y};
                uint32_t vl[2] = {vl2.x, vl2.y};
                mma16n8k8(o[tn], pa, vh);
                mma16n8k8(o[tn], pa, vl);
            }
        }
        __syncthreads();
        if (i < 30) issue_stage(i + 2);
    }

    // ---- epilogue: normalize and write g_OA A-images ----
    const int b = hb >> 4;
    const int h = hb & 15;
    const float inv0 = 1.0f / l0, inv1 = 1.0f / l1;
    const int rbase = b * 2048 + mb * 128 + w * 16 + g;
#pragma unroll
    for (int tn = 0; tn < 8; tn++) {
#pragma unroll
        for (int q = 0; q < 4; q++) {
            int d = h * 64 + tn * 8 + t4 * 2 + (q & 1);
            int row = rbase + ((q >> 1) << 3);
            float v = o[tn][q] * ((q < 2) ? inv0 : inv1);
            uint32_t hi = tf32_of(v);
            uint32_t lo = tf32_of(v - __uint_as_float(hi));
            char* blk = (char*)g_OA + (size_t)((row >> 7) * 32 + (d >> 5)) * 32768;
            uint32_t off = A_off(row & 127, d & 31);
            *reinterpret_cast<uint32_t*>(blk + off) = hi;
            *reinterpret_cast<uint32_t*>(blk + 16384 + off) = lo;
        }
    }
}

extern "C" void kernel_launch(void* const* d_in, const int* in_sizes, int n_in,
                              void* d_out, int out_size) {
    const float* x = (const float*)d_in[0];
    // d_in[1] = Wq (dead code in the reference dataflow)
    const float* Wk = (const float*)d_in[2];
    const float* Wv = (const float*)d_in[3];
    const float* Wo = (const float*)d_in[4];
    float* out = (float*)d_out;

    cudaFuncSetAttribute(proj_img_kernel, cudaFuncAttributeMaxDynamicSharedMemorySize,
                         GM_SMEM_BYTES);
    cudaFuncSetAttribute(oproj_img_kernel, cudaFuncAttributeMaxDynamicSharedMemorySize,
                         GM_SMEM_BYTES);
    cudaFuncSetAttribute(attn_mma_kernel, cudaFuncAttributeMaxDynamicSharedMemorySize,
                         ATT_SMEM_BYTES);

    // 1) Pre-split inputs into tf32 hi/lo fragment images
    split_kernel<<<dim3(32, 32, 4), 128>>>(x, Wk, Wv, Wo);

    // 2) K/V projections; epilogue writes K/V attention images directly
    proj_img_kernel<<<dim3(8, 32, 2), 512, GM_SMEM_BYTES>>>();

    // 3) Tensor-core attention, writes g_OA images
    attn_mma_kernel<<<dim3(16, 32), 256, ATT_SMEM_BYTES>>>();

    // 4) Output projection
    oproj_img_kernel<<<dim3(8, 32), 512, GM_SMEM_BYTES>>>(out);
}